// round 3
// baseline (speedup 1.0000x reference)
#include <cuda_runtime.h>

// Problem constants (fixed shapes for CRF_14379550507279):
//   emissions (B=512, S=2048, T=32) f32, tags (B,S) i32, mask (B,S) f32,
//   transitions (T,T) f32. Output: scalar f32.
// total = sum_b sum_t trans[tags[b,0],t]
//       + sum_{b,s,t} w(b,s) * em[b,s,t]        (w=1 at s==0, else mask[b,s])
//       + T * sum_{b,s>=1} trans[tags[b,s-1],tags[b,s]] * mask[b,s]

#define S_LEN 2048
#define S_MASK 2047
#define NTAGS 32

__device__ double g_acc;

__global__ void crf_init_kernel() { g_acc = 0.0; }

__global__ void __launch_bounds__(256) crf_main_kernel(
    const float4* __restrict__ em4,    // B*S*8 float4 chunks (32 floats / row)
    const int* __restrict__ tags,      // B*S
    const float* __restrict__ mask,    // B*S
    const float* __restrict__ trans,   // 32*32
    int total_chunks)                  // B*S*8
{
    __shared__ float s_trans[NTAGS * NTAGS];
    for (int i = threadIdx.x; i < NTAGS * NTAGS; i += blockDim.x)
        s_trans[i] = trans[i];
    __syncthreads();

    float acc = 0.0f;
    const int stride = gridDim.x * blockDim.x;
    for (int q = blockIdx.x * blockDim.x + threadIdx.x; q < total_chunks; q += stride) {
        const int row = q >> 3;          // (b,s) flat row index
        const int s   = row & S_MASK;    // position within sequence
        // weight: 1.0 at s==0 (mask[:,0] unused by reference), else mask[b,s]
        const float w = (s == 0) ? 1.0f : __ldg(&mask[row]);
        const float4 v = em4[q];
        acc += w * ((v.x + v.y) + (v.z + v.w));

        // Exactly one chunk per row (lane-in-row 0) handles the transition terms.
        if ((q & 7) == 0) {
            const int tc = __ldg(&tags[row]);
            if (s == 0) {
                // score0: full transition row for the first tag
                float ts = 0.0f;
                #pragma unroll
                for (int t = 0; t < NTAGS; t++) ts += s_trans[tc * NTAGS + t];
                acc += ts;
            } else {
                // scalar transition, counted NTAGS times by the reference's broadcast
                const int tp = __ldg(&tags[row - 1]);
                acc += (float)NTAGS * s_trans[tp * NTAGS + tc] * w;
            }
        }
    }

    // warp tree reduce
    #pragma unroll
    for (int o = 16; o > 0; o >>= 1)
        acc += __shfl_xor_sync(0xffffffffu, acc, o);

    __shared__ float warp_sums[8];
    const int wid = threadIdx.x >> 5;
    if ((threadIdx.x & 31) == 0) warp_sums[wid] = acc;
    __syncthreads();

    if (threadIdx.x == 0) {
        float b = 0.0f;
        #pragma unroll
        for (int i = 0; i < 8; i++) b += warp_sums[i];
        atomicAdd(&g_acc, (double)b);
    }
}

__global__ void crf_finalize_kernel(float* __restrict__ out) {
    out[0] = (float)g_acc;
}

extern "C" void kernel_launch(void* const* d_in, const int* in_sizes, int n_in,
                              void* d_out, int out_size) {
    const float* emissions   = (const float*)d_in[0];
    const int*   tags        = (const int*)d_in[1];
    const float* mask        = (const float*)d_in[2];
    const float* transitions = (const float*)d_in[3];

    const int total_elems  = in_sizes[0];      // B*S*T
    const int total_chunks = total_elems / 4;  // float4 chunks

    crf_init_kernel<<<1, 1>>>();

    // 1184 blocks * 256 threads = 148 SMs * 8 blocks: exactly one full wave.
    crf_main_kernel<<<1184, 256>>>(
        (const float4*)emissions, tags, mask, transitions, total_chunks);

    crf_finalize_kernel<<<1, 1>>>((float*)d_out);
}